// round 1
// baseline (speedup 1.0000x reference)
#include <cuda_runtime.h>

// ---------------------------------------------------------------------------
// OTPE single timestep.
// Inputs (metadata order): x[8192], W[8192,4096], u[4096], E[8192,4096],
//                          R_hat[8192,4096], g_bar[4096], ratio[1]
// Output (flattened tuple): s[4096], u_new[4096], E_new[8192*4096],
//                           R_new[8192*4096], g_bar_new[4096], ratio_new[1]
// ---------------------------------------------------------------------------

#define N_IN   8192
#define N_OUT  4096
// sigmoid(2.0) in fp32
#define SIG_TAU 0.88079707797788231f

#define NSPLIT 64
#define ROWS_PER_SPLIT (N_IN / NSPLIT)   // 128

// scratch (device globals; no allocation allowed)
__device__ __align__(16) float g_part[NSPLIT * N_OUT];
__device__ __align__(16) float g_sg[N_OUT];

// ---------------------------------------------------------------------------
// K1: split-K GEMV partials. grid (32, 64), block 128.
// Each thread owns one output column within one row-split of 128 rows.
// Coalesced: consecutive threads read consecutive W columns.
// ---------------------------------------------------------------------------
__global__ void __launch_bounds__(128)
otpe_gemv_partial(const float* __restrict__ W, const float* __restrict__ x) {
    __shared__ float sx[ROWS_PER_SPLIT];
    const int col   = blockIdx.x * 128 + threadIdx.x;
    const int split = blockIdx.y;
    const int r0    = split * ROWS_PER_SPLIT;

    sx[threadIdx.x] = x[r0 + threadIdx.x];
    __syncthreads();

    const float* Wp = W + (size_t)r0 * N_OUT + col;
    float a0 = 0.f, a1 = 0.f, a2 = 0.f, a3 = 0.f;
#pragma unroll 8
    for (int r = 0; r < ROWS_PER_SPLIT; r += 4) {
        a0 = fmaf(sx[r + 0], Wp[(size_t)(r + 0) * N_OUT], a0);
        a1 = fmaf(sx[r + 1], Wp[(size_t)(r + 1) * N_OUT], a1);
        a2 = fmaf(sx[r + 2], Wp[(size_t)(r + 2) * N_OUT], a2);
        a3 = fmaf(sx[r + 3], Wp[(size_t)(r + 3) * N_OUT], a3);
    }
    g_part[split * N_OUT + col] = (a0 + a1) + (a2 + a3);
}

// ---------------------------------------------------------------------------
// K2: deterministic reduce over splits + per-column post.
// grid 32, block 128 (4096 threads).
// ---------------------------------------------------------------------------
__global__ void __launch_bounds__(128)
otpe_column_post(const float* __restrict__ u,
                 const float* __restrict__ g_bar,
                 const float* __restrict__ ratio,
                 float* __restrict__ out_s,
                 float* __restrict__ out_u,
                 float* __restrict__ out_gbar,
                 float* __restrict__ out_ratio) {
    const int j = blockIdx.x * 128 + threadIdx.x;

    float acc = SIG_TAU * u[j];
#pragma unroll
    for (int s = 0; s < NSPLIT; ++s)
        acc += g_part[s * N_OUT + j];

    const float u_pre = acc;
    const float spike = (u_pre >= 1.0f) ? 1.0f : 0.0f;
    const float t  = fmaf(10.0f, fabsf(u_pre - 1.0f), 1.0f);
    const float sg = 1.0f / (t * t);

    g_sg[j]  = sg;
    out_s[j] = spike;
    out_u[j] = u_pre - spike;          // soft reset (V_TH = 1)

    const float r0        = SIG_TAU * ratio[0];
    const float ratio_new = r0 + 1.0f;
    const float r         = r0 / ratio_new;
    // ds_du_prev / sig_tau == sg
    out_gbar[j] = fmaf(r, g_bar[j], (1.0f - r) * sg);

    if (j == 0) out_ratio[0] = ratio_new;
}

// ---------------------------------------------------------------------------
// K3: fused E/R update, float4 vectorized. Reads old E once; serves both
// E_new and the dsd*E term of R_new. grid 32768, block 256.
// ---------------------------------------------------------------------------
__global__ void __launch_bounds__(256)
otpe_big_elem(const float4* __restrict__ E,
              const float4* __restrict__ R,
              const float*  __restrict__ x,
              float4* __restrict__ Eo,
              float4* __restrict__ Ro) {
    const long long v = (long long)blockIdx.x * 256 + threadIdx.x; // 0..8388607
    const int row  = (int)(v >> 10);        // 4096/4 = 1024 float4 per row
    const int colv = (int)(v & 1023);

    const float  xi  = __ldg(&x[row]);
    const float4 sg4 = reinterpret_cast<const float4*>(g_sg)[colv];
    const float4 e   = E[v];
    const float4 rr  = R[v];

    float4 eo, ro;
    eo.x = fmaf(SIG_TAU, e.x, xi);
    eo.y = fmaf(SIG_TAU, e.y, xi);
    eo.z = fmaf(SIG_TAU, e.z, xi);
    eo.w = fmaf(SIG_TAU, e.w, xi);

    // R_new = sig*R + (sg*sig)*E_old + x*sg
    ro.x = fmaf(SIG_TAU, rr.x, fmaf(sg4.x * SIG_TAU, e.x, xi * sg4.x));
    ro.y = fmaf(SIG_TAU, rr.y, fmaf(sg4.y * SIG_TAU, e.y, xi * sg4.y));
    ro.z = fmaf(SIG_TAU, rr.z, fmaf(sg4.z * SIG_TAU, e.z, xi * sg4.z));
    ro.w = fmaf(SIG_TAU, rr.w, fmaf(sg4.w * SIG_TAU, e.w, xi * sg4.w));

    Eo[v] = eo;
    Ro[v] = ro;
}

// ---------------------------------------------------------------------------
extern "C" void kernel_launch(void* const* d_in, const int* in_sizes, int n_in,
                              void* d_out, int out_size) {
    const float* x     = (const float*)d_in[0];
    const float* W     = (const float*)d_in[1];
    const float* u     = (const float*)d_in[2];
    const float* E     = (const float*)d_in[3];
    const float* R     = (const float*)d_in[4];
    const float* g_bar = (const float*)d_in[5];
    const float* ratio = (const float*)d_in[6];

    float* out       = (float*)d_out;
    float* out_s     = out;
    float* out_u     = out + N_OUT;
    float* out_E     = out + 2 * N_OUT;
    float* out_R     = out_E + (size_t)N_IN * N_OUT;
    float* out_gbar  = out_R + (size_t)N_IN * N_OUT;
    float* out_ratio = out_gbar + N_OUT;

    otpe_gemv_partial<<<dim3(N_OUT / 128, NSPLIT), 128>>>(W, x);
    otpe_column_post<<<N_OUT / 128, 128>>>(u, g_bar, ratio,
                                           out_s, out_u, out_gbar, out_ratio);

    const long long nvec = (long long)N_IN * N_OUT / 4;   // 8388608
    otpe_big_elem<<<(unsigned)(nvec / 256), 256>>>(
        (const float4*)E, (const float4*)R, x,
        (float4*)out_E, (float4*)out_R);
}